// round 3
// baseline (speedup 1.0000x reference)
#include <cuda_runtime.h>
#include <cuda_bf16.h>

// IntraAgg: segment-mean neighbor aggregation.
// inputs (metadata order):
//   d_in[0] features    float32 [100000*256]
//   d_in[1] neigh_idx   int32   [524288]
//   d_in[2] segment_ids int32   [524288] (sorted ascending)
//   d_in[3] self_feats  float32 [16384*256]
// output: float32 [16384*512] = concat(self - agg, agg)

#define D_FEAT 256
#define VEC    4                 // float4 per thread
#define TPB    (D_FEAT / VEC)    // 64 threads

__global__ __launch_bounds__(TPB) void intra_agg_kernel(
    const float* __restrict__ features,
    const int* __restrict__ neigh_idx,
    const int* __restrict__ seg_ids,
    const float* __restrict__ self_feats,
    float* __restrict__ out,
    int n_edges)
{
    const int b = blockIdx.x;
    const int tid = threadIdx.x;

    // Binary search [start, end): all threads identical (broadcast loads).
    int lo = 0, hi = n_edges;
    while (lo < hi) {
        int m = (lo + hi) >> 1;
        if (__ldg(seg_ids + m) < b) lo = m + 1; else hi = m;
    }
    const int start = lo;
    hi = n_edges;
    while (lo < hi) {
        int m = (lo + hi) >> 1;
        if (__ldg(seg_ids + m) <= b) lo = m + 1; else hi = m;
    }
    const int end = lo;

    float4 acc0 = make_float4(0.f, 0.f, 0.f, 0.f);
    float4 acc1 = make_float4(0.f, 0.f, 0.f, 0.f);
    float4 acc2 = make_float4(0.f, 0.f, 0.f, 0.f);
    float4 acc3 = make_float4(0.f, 0.f, 0.f, 0.f);

    const float4* __restrict__ feat4 = reinterpret_cast<const float4*>(features);

    int e = start;
    // unroll-by-4: four independent gather chains, loads front-batched for MLP
    for (; e + 3 < end; e += 4) {
        const int n0 = __ldg(neigh_idx + e);
        const int n1 = __ldg(neigh_idx + e + 1);
        const int n2 = __ldg(neigh_idx + e + 2);
        const int n3 = __ldg(neigh_idx + e + 3);
        const float4 f0 = __ldg(feat4 + (size_t)n0 * (D_FEAT / VEC) + tid);
        const float4 f1 = __ldg(feat4 + (size_t)n1 * (D_FEAT / VEC) + tid);
        const float4 f2 = __ldg(feat4 + (size_t)n2 * (D_FEAT / VEC) + tid);
        const float4 f3 = __ldg(feat4 + (size_t)n3 * (D_FEAT / VEC) + tid);
        acc0.x += f0.x; acc0.y += f0.y; acc0.z += f0.z; acc0.w += f0.w;
        acc1.x += f1.x; acc1.y += f1.y; acc1.z += f1.z; acc1.w += f1.w;
        acc2.x += f2.x; acc2.y += f2.y; acc2.z += f2.z; acc2.w += f2.w;
        acc3.x += f3.x; acc3.y += f3.y; acc3.z += f3.z; acc3.w += f3.w;
    }
    #pragma unroll 1
    for (; e < end; ++e) {
        const int n0 = __ldg(neigh_idx + e);
        const float4 f0 = __ldg(feat4 + (size_t)n0 * (D_FEAT / VEC) + tid);
        acc0.x += f0.x; acc0.y += f0.y; acc0.z += f0.z; acc0.w += f0.w;
    }

    float4 agg;
    const float inv = 1.0f / fmaxf((float)(end - start), 1.0f);
    agg.x = ((acc0.x + acc1.x) + (acc2.x + acc3.x)) * inv;
    agg.y = ((acc0.y + acc1.y) + (acc2.y + acc3.y)) * inv;
    agg.z = ((acc0.z + acc1.z) + (acc2.z + acc3.z)) * inv;
    agg.w = ((acc0.w + acc1.w) + (acc2.w + acc3.w)) * inv;

    const float4 s = __ldg(reinterpret_cast<const float4*>(self_feats + (size_t)b * D_FEAT) + tid);
    float4 diff;
    diff.x = s.x - agg.x; diff.y = s.y - agg.y;
    diff.z = s.z - agg.z; diff.w = s.w - agg.w;

    float* orow = out + (size_t)b * (2 * D_FEAT);
    reinterpret_cast<float4*>(orow)[tid] = diff;
    reinterpret_cast<float4*>(orow + D_FEAT)[tid] = agg;
}

extern "C" void kernel_launch(void* const* d_in, const int* in_sizes, int n_in,
                              void* d_out, int out_size)
{
    const float* features   = (const float*)d_in[0];
    const int*   neigh_idx  = (const int*)d_in[1];
    const int*   seg_ids    = (const int*)d_in[2];
    const float* self_feats = (const float*)d_in[3];
    float*       out        = (float*)d_out;

    const int n_edges = in_sizes[1];
    const int n_batch = in_sizes[3] / D_FEAT;   // 16384

    intra_agg_kernel<<<n_batch, TPB>>>(features, neigh_idx, seg_ids,
                                       self_feats, out, n_edges);
}

// round 4
// speedup vs baseline: 1.4969x; 1.4969x over previous
#include <cuda_runtime.h>
#include <cuda_bf16.h>

// IntraAgg: segment-mean neighbor aggregation.
//   d_in[0] features    float32 [100000*256]
//   d_in[1] neigh_idx   int32   [524288]
//   d_in[2] segment_ids int32   [524288] (sorted ascending)
//   d_in[3] self_feats  float32 [16384*256]
// output: float32 [16384*512] = concat(self - agg, agg)

#define D_FEAT  256
#define VEC     4                 // float4 per thread
#define TPB     (D_FEAT / VEC)    // 64 threads
#define N_BATCH 16384

// Precomputed CSR row offsets: seg_start[b] = first edge of segment b,
// seg_start[N_BATCH] = n_edges. Static device scratch (no allocs allowed).
__device__ int g_seg_start[N_BATCH + 1];

__global__ void seg_bounds_kernel(const int* __restrict__ seg_ids, int n_edges)
{
    const int e = blockIdx.x * blockDim.x + threadIdx.x;
    if (e >= n_edges) return;
    const int s_cur = __ldg(seg_ids + e);
    const int s_prev = (e == 0) ? -1 : __ldg(seg_ids + e - 1);
    // boundary: fill starts for every segment in (s_prev, s_cur]
    for (int b = s_prev + 1; b <= s_cur; ++b)
        g_seg_start[b] = e;
    if (e == n_edges - 1) {
        // tail: empty segments after the last edge, plus the sentinel
        for (int b = s_cur + 1; b <= N_BATCH; ++b)
            g_seg_start[b] = n_edges;
    }
}

__global__ __launch_bounds__(TPB) void intra_agg_kernel(
    const float* __restrict__ features,
    const int* __restrict__ neigh_idx,
    const float* __restrict__ self_feats,
    float* __restrict__ out)
{
    const int b = blockIdx.x;
    const int tid = threadIdx.x;

    const int start = g_seg_start[b];
    const int end   = g_seg_start[b + 1];

    float4 acc0 = make_float4(0.f, 0.f, 0.f, 0.f);
    float4 acc1 = make_float4(0.f, 0.f, 0.f, 0.f);

    const float4* __restrict__ feat4 = reinterpret_cast<const float4*>(features);

    int e = start;
    // unroll-by-2: two independent gather chains (32 regs sweet spot — do NOT
    // widen; unroll-4 cost occupancy and regressed, see R3)
    for (; e + 1 < end; e += 2) {
        const int n0 = __ldg(neigh_idx + e);
        const int n1 = __ldg(neigh_idx + e + 1);
        const float4 f0 = __ldg(feat4 + (size_t)n0 * (D_FEAT / VEC) + tid);
        const float4 f1 = __ldg(feat4 + (size_t)n1 * (D_FEAT / VEC) + tid);
        acc0.x += f0.x; acc0.y += f0.y; acc0.z += f0.z; acc0.w += f0.w;
        acc1.x += f1.x; acc1.y += f1.y; acc1.z += f1.z; acc1.w += f1.w;
    }
    if (e < end) {
        const int n0 = __ldg(neigh_idx + e);
        const float4 f0 = __ldg(feat4 + (size_t)n0 * (D_FEAT / VEC) + tid);
        acc0.x += f0.x; acc0.y += f0.y; acc0.z += f0.z; acc0.w += f0.w;
    }

    float4 agg;
    const float inv = 1.0f / fmaxf((float)(end - start), 1.0f);
    agg.x = (acc0.x + acc1.x) * inv;
    agg.y = (acc0.y + acc1.y) * inv;
    agg.z = (acc0.z + acc1.z) * inv;
    agg.w = (acc0.w + acc1.w) * inv;

    const float4 s = __ldg(reinterpret_cast<const float4*>(self_feats + (size_t)b * D_FEAT) + tid);
    float4 diff;
    diff.x = s.x - agg.x; diff.y = s.y - agg.y;
    diff.z = s.z - agg.z; diff.w = s.w - agg.w;

    float* orow = out + (size_t)b * (2 * D_FEAT);
    reinterpret_cast<float4*>(orow)[tid] = diff;
    reinterpret_cast<float4*>(orow + D_FEAT)[tid] = agg;
}

extern "C" void kernel_launch(void* const* d_in, const int* in_sizes, int n_in,
                              void* d_out, int out_size)
{
    const float* features   = (const float*)d_in[0];
    const int*   neigh_idx  = (const int*)d_in[1];
    const int*   seg_ids    = (const int*)d_in[2];
    const float* self_feats = (const float*)d_in[3];
    float*       out        = (float*)d_out;

    const int n_edges = in_sizes[1];
    const int n_batch = in_sizes[3] / D_FEAT;   // 16384

    seg_bounds_kernel<<<(n_edges + 255) / 256, 256>>>(seg_ids, n_edges);
    intra_agg_kernel<<<n_batch, TPB>>>(features, neigh_idx, self_feats, out);
}